// round 2
// baseline (speedup 1.0000x reference)
#include <cuda_runtime.h>

// Problem constants
#define B_  2
#define S_  2048
#define D_  1024
#define H_  16
#define HD_ 64
#define SCALE_ 0.125f   // 64^-0.5

// Scratch (device globals; no allocation allowed)
__device__ float g_q[(size_t)B_ * H_ * S_ * HD_];    // [B,H,S,HD]
__device__ float g_k[(size_t)B_ * H_ * S_ * HD_];    // [B,H,S,HD]
__device__ float g_v[(size_t)B_ * H_ * S_ * HD_];    // [B,H,S,HD]
__device__ float g_att[(size_t)B_ * S_ * D_];        // [B,S,D]

// ---------------------------------------------------------------------------
// Tiled SGEMM: C[M,N] = A[M,K=1024] * W[K,N] + bias[N]
// BM=BN=128, BK=8, 256 threads, 8x8 microtile.
// MODE 0: scatter into g_q/g_k/g_v ([B,H,S,HD]); MODE 1: dense store to Cout.
// ---------------------------------------------------------------------------
template <int N, int MODE>
__global__ __launch_bounds__(256) void sgemm_kernel(const float* __restrict__ A,
                                                    const float* __restrict__ W,
                                                    const float* __restrict__ bias,
                                                    float* __restrict__ Cout) {
    constexpr int K = 1024;
    __shared__ float As[8][128];   // [k][m]
    __shared__ float Bs[8][128];   // [k][n]

    const int tid = threadIdx.x;
    const int bm = blockIdx.y * 128;
    const int bn = blockIdx.x * 128;
    const int ty = tid >> 4;          // 0..15
    const int tx = tid & 15;          // 0..15

    // load indices
    const int arow = tid >> 1;            // 0..127
    const int acol = (tid & 1) * 4;       // 0 or 4
    const int brow = tid >> 5;            // 0..7
    const int bcol = (tid & 31) * 4;      // 0..124

    const float* Aptr = A + (size_t)(bm + arow) * K + acol;
    const float* Bptr = W + (size_t)brow * N + bn + bcol;

    float acc[8][8];
#pragma unroll
    for (int i = 0; i < 8; i++)
#pragma unroll
        for (int j = 0; j < 8; j++) acc[i][j] = 0.0f;

    for (int k0 = 0; k0 < K; k0 += 8) {
        float4 av = *reinterpret_cast<const float4*>(Aptr);
        Aptr += 8;
        As[acol + 0][arow] = av.x;
        As[acol + 1][arow] = av.y;
        As[acol + 2][arow] = av.z;
        As[acol + 3][arow] = av.w;

        float4 bv = *reinterpret_cast<const float4*>(Bptr);
        Bptr += (size_t)8 * N;
        *reinterpret_cast<float4*>(&Bs[brow][bcol]) = bv;
        __syncthreads();

#pragma unroll
        for (int kk = 0; kk < 8; kk++) {
            float4 a0 = *reinterpret_cast<const float4*>(&As[kk][ty * 8]);
            float4 a1 = *reinterpret_cast<const float4*>(&As[kk][ty * 8 + 4]);
            float4 b0 = *reinterpret_cast<const float4*>(&Bs[kk][tx * 8]);
            float4 b1 = *reinterpret_cast<const float4*>(&Bs[kk][tx * 8 + 4]);
            float a[8] = {a0.x, a0.y, a0.z, a0.w, a1.x, a1.y, a1.z, a1.w};
            float b[8] = {b0.x, b0.y, b0.z, b0.w, b1.x, b1.y, b1.z, b1.w};
#pragma unroll
            for (int i = 0; i < 8; i++)
#pragma unroll
                for (int j = 0; j < 8; j++) acc[i][j] = fmaf(a[i], b[j], acc[i][j]);
        }
        __syncthreads();
    }

    // epilogue
#pragma unroll
    for (int i = 0; i < 8; i++) {
        const int row = bm + ty * 8 + i;       // m index
#pragma unroll
        for (int j = 0; j < 8; j++) {
            const int col = bn + tx * 8 + j;   // n index
            float v = acc[i][j] + bias[col];
            if (MODE == 0) {
                // scatter into [B,H,S,HD]
                const int which = col / D_;    // 0=q 1=k 2=v
                const int d     = col - which * D_;
                const int h     = d >> 6;      // /HD
                const int hd    = d & 63;
                const int b     = row >> 11;   // /S
                const int s     = row & 2047;
                const size_t dst = (((size_t)b * H_ + h) * S_ + s) * HD_ + hd;
                if (which == 0)      g_q[dst] = v;
                else if (which == 1) g_k[dst] = v;
                else                 g_v[dst] = v;
            } else {
                Cout[(size_t)row * N + col] = v;
            }
        }
    }
}

// ---------------------------------------------------------------------------
// Flash attention: per (b,h,q-tile of 64), stream K/V tiles of 64 rows.
// 256 threads = 16x16 grid, each thread owns a 4x4 score/output microtile.
// Online softmax; row reductions via shfl over the 16-lane tx group.
// Dynamic smem: Qs/Ks/Vs/Ps each [64][65] floats = 66,560 B.
// ---------------------------------------------------------------------------
__global__ __launch_bounds__(256) void attn_kernel() {
    extern __shared__ float sm[];
    float* Qs = sm;                 // [64][65]
    float* Ks = sm + 64 * 65;       // [64][65]
    float* Vs = sm + 2 * 64 * 65;   // [64][65]
    float* Ps = sm + 3 * 64 * 65;   // [64][65]

    const int b  = blockIdx.z;
    const int h  = blockIdx.y;
    const int q0 = blockIdx.x * 64;

    const size_t head_off = ((size_t)b * H_ + h) * S_ * HD_;
    const float* Qg = g_q + head_off;
    const float* Kg = g_k + head_off;
    const float* Vg = g_v + head_off;

    const int tid = threadIdx.x;
    const int ty = tid >> 4;   // 0..15
    const int tx = tid & 15;   // 0..15

    // Load Q tile (64x64) once
    for (int i = tid; i < 64 * 16; i += 256) {
        const int r = i >> 4, c = (i & 15) * 4;
        float4 v = *reinterpret_cast<const float4*>(Qg + (size_t)(q0 + r) * HD_ + c);
        float* dst = Qs + r * 65 + c;
        dst[0] = v.x; dst[1] = v.y; dst[2] = v.z; dst[3] = v.w;
    }

    float m_i[4], l_i[4], O[4][4];
#pragma unroll
    for (int i = 0; i < 4; i++) {
        m_i[i] = -1e30f; l_i[i] = 0.0f;
#pragma unroll
        for (int j = 0; j < 4; j++) O[i][j] = 0.0f;
    }

    for (int kt = 0; kt < S_; kt += 64) {
        // Load K and V tiles
        for (int i = tid; i < 64 * 16; i += 256) {
            const int r = i >> 4, c = (i & 15) * 4;
            float4 kv = *reinterpret_cast<const float4*>(Kg + (size_t)(kt + r) * HD_ + c);
            float* kd = Ks + r * 65 + c;
            kd[0] = kv.x; kd[1] = kv.y; kd[2] = kv.z; kd[3] = kv.w;
            float4 vv = *reinterpret_cast<const float4*>(Vg + (size_t)(kt + r) * HD_ + c);
            float* vd = Vs + r * 65 + c;
            vd[0] = vv.x; vd[1] = vv.y; vd[2] = vv.z; vd[3] = vv.w;
        }
        __syncthreads();

        // Scores: s[i][j] = sum_d Q[ty*4+i][d] * K[tx*4+j][d]
        float s[4][4];
#pragma unroll
        for (int i = 0; i < 4; i++)
#pragma unroll
            for (int j = 0; j < 4; j++) s[i][j] = 0.0f;

#pragma unroll 8
        for (int d = 0; d < HD_; d++) {
            float qv[4], kvv[4];
#pragma unroll
            for (int i = 0; i < 4; i++) qv[i] = Qs[(ty * 4 + i) * 65 + d];
#pragma unroll
            for (int j = 0; j < 4; j++) kvv[j] = Ks[(tx * 4 + j) * 65 + d];
#pragma unroll
            for (int i = 0; i < 4; i++)
#pragma unroll
                for (int j = 0; j < 4; j++) s[i][j] = fmaf(qv[i], kvv[j], s[i][j]);
        }

        // Online softmax update per row
        float p[4][4];
#pragma unroll
        for (int i = 0; i < 4; i++) {
#pragma unroll
            for (int j = 0; j < 4; j++) s[i][j] *= SCALE_;
            float rm = fmaxf(fmaxf(s[i][0], s[i][1]), fmaxf(s[i][2], s[i][3]));
#pragma unroll
            for (int off = 1; off < 16; off <<= 1)
                rm = fmaxf(rm, __shfl_xor_sync(0xffffffffu, rm, off));
            const float mnew  = fmaxf(m_i[i], rm);
            const float alpha = __expf(m_i[i] - mnew);
            float rs = 0.0f;
#pragma unroll
            for (int j = 0; j < 4; j++) { p[i][j] = __expf(s[i][j] - mnew); rs += p[i][j]; }
#pragma unroll
            for (int off = 1; off < 16; off <<= 1)
                rs += __shfl_xor_sync(0xffffffffu, rs, off);
            l_i[i] = l_i[i] * alpha + rs;
            m_i[i] = mnew;
#pragma unroll
            for (int j = 0; j < 4; j++) O[i][j] *= alpha;
        }

        // Stage P through smem for the PV GEMM
#pragma unroll
        for (int i = 0; i < 4; i++)
#pragma unroll
            for (int j = 0; j < 4; j++)
                Ps[(ty * 4 + i) * 65 + (tx * 4 + j)] = p[i][j];
        __syncthreads();

        // O[i][c] += sum_k P[row][k] * V[k][c]
#pragma unroll 8
        for (int kk = 0; kk < 64; kk++) {
            float pk[4], vv[4];
#pragma unroll
            for (int i = 0; i < 4; i++) pk[i] = Ps[(ty * 4 + i) * 65 + kk];
#pragma unroll
            for (int j = 0; j < 4; j++) vv[j] = Vs[kk * 65 + tx * 4 + j];
#pragma unroll
            for (int i = 0; i < 4; i++)
#pragma unroll
                for (int j = 0; j < 4; j++) O[i][j] = fmaf(pk[i], vv[j], O[i][j]);
        }
        __syncthreads();
    }

    // Normalize and write to g_att [B,S,D] with head-interleave
#pragma unroll
    for (int i = 0; i < 4; i++) {
        const float inv = 1.0f / l_i[i];
        const int s_idx = q0 + ty * 4 + i;
        float* dst = g_att + ((size_t)b * S_ + s_idx) * D_ + h * HD_ + tx * 4;
#pragma unroll
        for (int j = 0; j < 4; j++) dst[j] = O[i][j] * inv;
    }
}

// ---------------------------------------------------------------------------
extern "C" void kernel_launch(void* const* d_in, const int* in_sizes, int n_in,
                              void* d_out, int out_size) {
    (void)in_sizes; (void)n_in; (void)out_size;
    const float* x     = (const float*)d_in[0];
    const float* Wqkv  = (const float*)d_in[1];
    const float* bqkv  = (const float*)d_in[2];
    const float* Wproj = (const float*)d_in[3];
    const float* bproj = (const float*)d_in[4];
    float* out = (float*)d_out;

    // Device address of g_att (passing the __device__ symbol directly from
    // host code passes the host shadow address — that was the R1 bug).
    float* att_dev = nullptr;
    cudaGetSymbolAddress((void**)&att_dev, g_att);

    // QKV GEMM: [4096,1024] x [1024,3072] -> scatter to g_q/g_k/g_v
    {
        dim3 grid(3 * D_ / 128, (B_ * S_) / 128);
        sgemm_kernel<3 * D_, 0><<<grid, 256>>>(x, Wqkv, bqkv, nullptr);
    }

    // Attention
    {
        const int smem = 4 * 64 * 65 * (int)sizeof(float);  // 66,560 B
        cudaFuncSetAttribute(attn_kernel, cudaFuncAttributeMaxDynamicSharedMemorySize, smem);
        dim3 grid(S_ / 64, H_, B_);
        attn_kernel<<<grid, 256, smem>>>();
    }

    // Output projection: [4096,1024] x [1024,1024] -> d_out
    {
        dim3 grid(D_ / 128, (B_ * S_) / 128);
        sgemm_kernel<D_, 1><<<grid, 256>>>(att_dev, Wproj, bproj, out);
    }
}

// round 4
// speedup vs baseline: 2.6776x; 2.6776x over previous
#include <cuda_runtime.h>
#include <cstdint>

#define B_  2
#define S_  2048
#define D_  1024
#define H_  16
#define HD_ 64
#define SCALE_ 0.125f

// Scratch
__device__ float g_q[(size_t)B_ * H_ * S_ * HD_];
__device__ float g_k[(size_t)B_ * H_ * S_ * HD_];
__device__ float g_v[(size_t)B_ * H_ * S_ * HD_];
__device__ float g_att[(size_t)B_ * S_ * D_];
__device__ float g_wqkvt[(size_t)3 * D_ * D_];   // Wqkv^T  [3072,1024]
__device__ float g_wprojt[(size_t)D_ * D_];      // Wproj^T [1024,1024]

__device__ __forceinline__ uint32_t f2tf32(float x) {
    uint32_t u;
    asm("cvt.rna.tf32.f32 %0, %1;" : "=r"(u) : "f"(x));
    return u;
}

// D = A(16x8 tf32 row) * B(8x8 tf32 col) + D, fp32 accum
__device__ __forceinline__ void mma8(float d[4], const uint32_t a[4], uint32_t b0, uint32_t b1) {
    asm volatile(
        "mma.sync.aligned.m16n8k8.row.col.f32.tf32.tf32.f32 "
        "{%0,%1,%2,%3},{%4,%5,%6,%7},{%8,%9},{%0,%1,%2,%3};"
        : "+f"(d[0]), "+f"(d[1]), "+f"(d[2]), "+f"(d[3])
        : "r"(a[0]), "r"(a[1]), "r"(a[2]), "r"(a[3]), "r"(b0), "r"(b1));
}

// ---------------------------------------------------------------------------
// Transpose: out[C,R] = in[R,C]
// ---------------------------------------------------------------------------
__global__ __launch_bounds__(256) void transpose_kernel(const float* __restrict__ in,
                                                        float* __restrict__ out,
                                                        int R, int C) {
    __shared__ float t[32][33];
    const int bx = blockIdx.x * 32, by = blockIdx.y * 32;
    for (int i = threadIdx.y; i < 32; i += 8)
        t[i][threadIdx.x] = in[(size_t)(by + i) * C + bx + threadIdx.x];
    __syncthreads();
    for (int i = threadIdx.y; i < 32; i += 8)
        out[(size_t)(bx + i) * R + by + threadIdx.x] = t[threadIdx.x][i];
}

// ---------------------------------------------------------------------------
// mma.sync tf32 GEMM: C[M,N] = A[M,1024] @ Bt[N,1024]^T + bias
// 128x128 CTA tile, 256 thr (8 warps as 2x4), warp tile 64x32, BK=32.
// MODE 0: scatter into g_q/g_k/g_v; MODE 1: dense store.
// ---------------------------------------------------------------------------
template <int NTOT, int MODE>
__global__ __launch_bounds__(256) void mma_gemm(const float* __restrict__ A,
                                                const float* __restrict__ Bt,
                                                const float* __restrict__ bias,
                                                float* __restrict__ Cout) {
    constexpr int K = 1024;
    __shared__ uint32_t As[128][36];   // [m][k]
    __shared__ uint32_t Bs[128][36];   // [n][k]

    const int tid = threadIdx.x, lane = tid & 31, w = tid >> 5;
    const int bm = blockIdx.y * 128, bn = blockIdx.x * 128;
    const int wm = (w & 1) * 64, wn = (w >> 1) * 32;
    const int r = lane >> 2, c = lane & 3;

    float acc[4][4][4];
#pragma unroll
    for (int mi = 0; mi < 4; mi++)
#pragma unroll
        for (int ni = 0; ni < 4; ni++)
#pragma unroll
            for (int q = 0; q < 4; q++) acc[mi][ni][q] = 0.0f;

    for (int k0 = 0; k0 < K; k0 += 32) {
#pragma unroll
        for (int it = 0; it < 4; it++) {
            const int slot = tid + it * 256;
            const int row = slot >> 3, c4 = (slot & 7) * 4;
            float4 va = *reinterpret_cast<const float4*>(A + (size_t)(bm + row) * K + k0 + c4);
            As[row][c4 + 0] = f2tf32(va.x); As[row][c4 + 1] = f2tf32(va.y);
            As[row][c4 + 2] = f2tf32(va.z); As[row][c4 + 3] = f2tf32(va.w);
            float4 vb = *reinterpret_cast<const float4*>(Bt + (size_t)(bn + row) * K + k0 + c4);
            Bs[row][c4 + 0] = f2tf32(vb.x); Bs[row][c4 + 1] = f2tf32(vb.y);
            Bs[row][c4 + 2] = f2tf32(vb.z); Bs[row][c4 + 3] = f2tf32(vb.w);
        }
        __syncthreads();

#pragma unroll
        for (int ks = 0; ks < 4; ks++) {
            const int k = ks * 8;
            uint32_t af[4][4];
#pragma unroll
            for (int mi = 0; mi < 4; mi++) {
                af[mi][0] = As[wm + mi * 16 + r][k + c];
                af[mi][1] = As[wm + mi * 16 + 8 + r][k + c];
                af[mi][2] = As[wm + mi * 16 + r][k + c + 4];
                af[mi][3] = As[wm + mi * 16 + 8 + r][k + c + 4];
            }
            uint32_t bf[4][2];
#pragma unroll
            for (int ni = 0; ni < 4; ni++) {
                bf[ni][0] = Bs[wn + ni * 8 + r][k + c];
                bf[ni][1] = Bs[wn + ni * 8 + r][k + c + 4];
            }
#pragma unroll
            for (int mi = 0; mi < 4; mi++)
#pragma unroll
                for (int ni = 0; ni < 4; ni++)
                    mma8(acc[mi][ni], af[mi], bf[ni][0], bf[ni][1]);
        }
        __syncthreads();
    }

    // Epilogue
    const int c2 = (lane & 3) * 2;
#pragma unroll
    for (int mi = 0; mi < 4; mi++) {
#pragma unroll
        for (int ni = 0; ni < 4; ni++) {
            const int col = bn + wn + ni * 8 + c2;
            const float bi0 = bias[col], bi1 = bias[col + 1];
#pragma unroll
            for (int half = 0; half < 2; half++) {
                const int row = bm + wm + mi * 16 + r + half * 8;
                const float v0 = acc[mi][ni][half * 2 + 0] + bi0;
                const float v1 = acc[mi][ni][half * 2 + 1] + bi1;
                if (MODE == 0) {
                    const int which = col >> 10;
                    const int d     = col & 1023;
                    const int h     = d >> 6;
                    const int hd    = d & 63;
                    const int b     = row >> 11;
                    const int s     = row & 2047;
                    const size_t dst = (((size_t)b * H_ + h) * S_ + s) * HD_ + hd;
                    float2 v = {v0, v1};
                    if (which == 0)      *reinterpret_cast<float2*>(g_q + dst) = v;
                    else if (which == 1) *reinterpret_cast<float2*>(g_k + dst) = v;
                    else                 *reinterpret_cast<float2*>(g_v + dst) = v;
                } else {
                    float2 v = {v0, v1};
                    *reinterpret_cast<float2*>(Cout + (size_t)row * NTOT + col) = v;
                }
            }
        }
    }
}

// ---------------------------------------------------------------------------
// Flash attention with mma.sync tf32.
// CTA: 256 thr (8 warps), Br=128 q-rows, Bc=64 k-cols, HD=64.
// Warp w owns q-rows [w*16, w*16+16). O frags persistent across k-tiles.
// SMEM (uint32 tf32 bits / fp32 bits): Qs[128][68], Ks[64][68], Vs[64][68] (d,k),
// Ss[128][68], plus m/l/alpha[128].
// ---------------------------------------------------------------------------
__global__ __launch_bounds__(256) void attn_mma() {
    extern __shared__ uint32_t smu[];
    uint32_t* Qs = smu;                    // [128][68]
    uint32_t* Ks = Qs + 128 * 68;          // [64][68]
    uint32_t* Vs = Ks + 64 * 68;           // [64][68]  (row=d, col=k)
    uint32_t* Ss = Vs + 64 * 68;           // [128][68]
    float* m_sm  = reinterpret_cast<float*>(Ss + 128 * 68);   // [128]
    float* l_sm  = m_sm + 128;
    float* al_sm = l_sm + 128;

    const int b  = blockIdx.z;
    const int h  = blockIdx.y;
    const int q0 = blockIdx.x * 128;

    const size_t head_off = ((size_t)b * H_ + h) * S_ * HD_;
    const float* Qg = g_q + head_off;
    const float* Kg = g_k + head_off;
    const float* Vg = g_v + head_off;

    const int tid = threadIdx.x, lane = tid & 31, w = tid >> 5;
    const int wrow = w * 16;
    const int r = lane >> 2, c = lane & 3;

    // Load Q tile (128x64) once, tf32
#pragma unroll
    for (int it = 0; it < 8; it++) {
        const int slot = tid + it * 256;
        const int row = slot >> 4, c4 = (slot & 15) * 4;
        float4 v = *reinterpret_cast<const float4*>(Qg + (size_t)(q0 + row) * HD_ + c4);
        uint32_t* d = Qs + row * 68 + c4;
        d[0] = f2tf32(v.x); d[1] = f2tf32(v.y); d[2] = f2tf32(v.z); d[3] = f2tf32(v.w);
    }
    if (tid < 128) { m_sm[tid] = -1e30f; l_sm[tid] = 0.0f; }

    float O[8][4];
#pragma unroll
    for (int ni = 0; ni < 8; ni++)
#pragma unroll
        for (int q = 0; q < 4; q++) O[ni][q] = 0.0f;

    for (int kt = 0; kt < S_; kt += 64) {
        __syncthreads();
        // Load K (row=k-idx, col=d) and V transposed (row=d, col=k-idx)
#pragma unroll
        for (int it = 0; it < 4; it++) {
            const int slot = tid + it * 256;
            const int row = slot >> 4, c4 = (slot & 15) * 4;
            float4 kv = *reinterpret_cast<const float4*>(Kg + (size_t)(kt + row) * HD_ + c4);
            uint32_t* kd = Ks + row * 68 + c4;
            kd[0] = f2tf32(kv.x); kd[1] = f2tf32(kv.y); kd[2] = f2tf32(kv.z); kd[3] = f2tf32(kv.w);
            float4 vv = *reinterpret_cast<const float4*>(Vg + (size_t)(kt + row) * HD_ + c4);
            Vs[(c4 + 0) * 68 + row] = f2tf32(vv.x);
            Vs[(c4 + 1) * 68 + row] = f2tf32(vv.y);
            Vs[(c4 + 2) * 68 + row] = f2tf32(vv.z);
            Vs[(c4 + 3) * 68 + row] = f2tf32(vv.w);
        }
        __syncthreads();

        // S = Q @ K^T for this warp's 16 rows x 64 cols
        float sf[8][4];
#pragma unroll
        for (int ni = 0; ni < 8; ni++)
#pragma unroll
            for (int q = 0; q < 4; q++) sf[ni][q] = 0.0f;
#pragma unroll
        for (int ks = 0; ks < 8; ks++) {
            const int k = ks * 8;
            uint32_t af[4];
            af[0] = Qs[(wrow + r) * 68 + k + c];
            af[1] = Qs[(wrow + 8 + r) * 68 + k + c];
            af[2] = Qs[(wrow + r) * 68 + k + c + 4];
            af[3] = Qs[(wrow + 8 + r) * 68 + k + c + 4];
#pragma unroll
            for (int ni = 0; ni < 8; ni++) {
                uint32_t b0 = Ks[(ni * 8 + r) * 68 + k + c];
                uint32_t b1 = Ks[(ni * 8 + r) * 68 + k + c + 4];
                mma8(sf[ni], af, b0, b1);
            }
        }
        // stage scaled scores (fp32 bits) to Ss
        const int c2 = (lane & 3) * 2;
#pragma unroll
        for (int ni = 0; ni < 8; ni++) {
            const int col = ni * 8 + c2;
            float2 v0 = {sf[ni][0] * SCALE_, sf[ni][1] * SCALE_};
            float2 v1 = {sf[ni][2] * SCALE_, sf[ni][3] * SCALE_};
            *reinterpret_cast<float2*>(Ss + (wrow + r) * 68 + col)     = v0;
            *reinterpret_cast<float2*>(Ss + (wrow + 8 + r) * 68 + col) = v1;
        }
        __syncthreads();

        // Online softmax: 2 threads per row, 32 cols each
        {
            const int row = tid >> 1, half = tid & 1;
            float* srow = reinterpret_cast<float*>(Ss) + row * 68 + half * 32;
            float4 sv[8];
            float mloc = -1e30f;
#pragma unroll
            for (int i = 0; i < 8; i++) {
                sv[i] = *reinterpret_cast<const float4*>(srow + i * 4);
                mloc = fmaxf(mloc, fmaxf(fmaxf(sv[i].x, sv[i].y), fmaxf(sv[i].z, sv[i].w)));
            }
            mloc = fmaxf(mloc, __shfl_xor_sync(0xffffffffu, mloc, 1));
            const float mold = m_sm[row];
            const float mnew = fmaxf(mold, mloc);
            const float alpha = __expf(mold - mnew);
            float ls = 0.0f;
#pragma unroll
            for (int i = 0; i < 8; i++) {
                float p0 = __expf(sv[i].x - mnew);
                float p1 = __expf(sv[i].y - mnew);
                float p2 = __expf(sv[i].z - mnew);
                float p3 = __expf(sv[i].w - mnew);
                ls += (p0 + p1) + (p2 + p3);
                uint32_t* pd = Ss + row * 68 + half * 32 + i * 4;
                pd[0] = f2tf32(p0); pd[1] = f2tf32(p1); pd[2] = f2tf32(p2); pd[3] = f2tf32(p3);
            }
            ls += __shfl_xor_sync(0xffffffffu, ls, 1);
            if (half == 0) {
                m_sm[row]  = mnew;
                l_sm[row]  = l_sm[row] * alpha + ls;
                al_sm[row] = alpha;
            }
        }
        __syncthreads();

        // O = alpha*O + P @ V
        const float a0 = al_sm[wrow + r];
        const float a1 = al_sm[wrow + 8 + r];
#pragma unroll
        for (int ni = 0; ni < 8; ni++) {
            O[ni][0] *= a0; O[ni][1] *= a0; O[ni][2] *= a1; O[ni][3] *= a1;
        }
#pragma unroll
        for (int ks = 0; ks < 8; ks++) {
            const int k = ks * 8;
            uint32_t af[4];
            af[0] = Ss[(wrow + r) * 68 + k + c];
            af[1] = Ss[(wrow + 8 + r) * 68 + k + c];
            af[2] = Ss[(wrow + r) * 68 + k + c + 4];
            af[3] = Ss[(wrow + 8 + r) * 68 + k + c + 4];
#pragma unroll
            for (int ni = 0; ni < 8; ni++) {
                uint32_t b0 = Vs[(ni * 8 + r) * 68 + k + c];
                uint32_t b1 = Vs[(ni * 8 + r) * 68 + k + c + 4];
                mma8(O[ni], af, b0, b1);
            }
        }
    }

    // Normalize and write out
    const float il0 = 1.0f / l_sm[wrow + r];
    const float il1 = 1.0f / l_sm[wrow + 8 + r];
    const int c2 = (lane & 3) * 2;
#pragma unroll
    for (int ni = 0; ni < 8; ni++) {
        const int col = h * HD_ + ni * 8 + c2;
        const int row0 = q0 + wrow + r;
        float2 v0 = {O[ni][0] * il0, O[ni][1] * il0};
        float2 v1 = {O[ni][2] * il1, O[ni][3] * il1};
        *reinterpret_cast<float2*>(g_att + ((size_t)b * S_ + row0) * D_ + col)       = v0;
        *reinterpret_cast<float2*>(g_att + ((size_t)b * S_ + row0 + 8) * D_ + col)   = v1;
    }
}

// ---------------------------------------------------------------------------
extern "C" void kernel_launch(void* const* d_in, const int* in_sizes, int n_in,
                              void* d_out, int out_size) {
    (void)in_sizes; (void)n_in; (void)out_size;
    const float* x     = (const float*)d_in[0];
    const float* Wqkv  = (const float*)d_in[1];
    const float* bqkv  = (const float*)d_in[2];
    const float* Wproj = (const float*)d_in[3];
    const float* bproj = (const float*)d_in[4];
    float* out = (float*)d_out;

    float *att_dev = nullptr, *wqkvt_dev = nullptr, *wprojt_dev = nullptr;
    cudaGetSymbolAddress((void**)&att_dev,    g_att);
    cudaGetSymbolAddress((void**)&wqkvt_dev,  g_wqkvt);
    cudaGetSymbolAddress((void**)&wprojt_dev, g_wprojt);

    // Transpose weights to K-major [N,K]
    {
        dim3 blk(32, 8);
        transpose_kernel<<<dim3(3 * D_ / 32, D_ / 32), blk>>>(Wqkv, wqkvt_dev, D_, 3 * D_);
        transpose_kernel<<<dim3(D_ / 32, D_ / 32), blk>>>(Wproj, wprojt_dev, D_, D_);
    }

    // QKV GEMM (mma.sync tf32)
    {
        dim3 grid(3 * D_ / 128, (B_ * S_) / 128);
        mma_gemm<3 * D_, 0><<<grid, 256>>>(x, wqkvt_dev, bqkv, nullptr);
    }

    // Attention (mma.sync tf32)
    {
        const int smem = (128 * 68 + 64 * 68 + 64 * 68 + 128 * 68) * 4 + 3 * 128 * 4; // 105,984
        cudaFuncSetAttribute(attn_mma, cudaFuncAttributeMaxDynamicSharedMemorySize, smem);
        dim3 grid(S_ / 128, H_, B_);
        attn_mma<<<grid, 256, smem>>>();
    }

    // Output projection (mma.sync tf32)
    {
        dim3 grid(D_ / 128, (B_ * S_) / 128);
        mma_gemm<D_, 1><<<grid, 256>>>(att_dev, wprojt_dev, bproj, out);
    }
}

// round 5
// speedup vs baseline: 2.9973x; 1.1194x over previous
#include <cuda_runtime.h>
#include <cstdint>

#define B_  2
#define S_  2048
#define D_  1024
#define H_  16
#define HD_ 64
#define SCALE_ 0.125f

// Scratch
__device__ float g_q[(size_t)B_ * H_ * S_ * HD_];
__device__ float g_k[(size_t)B_ * H_ * S_ * HD_];
__device__ float g_v[(size_t)B_ * H_ * S_ * HD_];
__device__ float g_att[(size_t)B_ * S_ * D_];
__device__ float g_wqkvt[(size_t)3 * D_ * D_];   // Wqkv^T  [3072,1024]
__device__ float g_wprojt[(size_t)D_ * D_];      // Wproj^T [1024,1024]

__device__ __forceinline__ uint32_t f2tf32(float x) {
    uint32_t u;
    asm("cvt.rna.tf32.f32 %0, %1;" : "=r"(u) : "f"(x));
    return u;
}

// D = A(16x8 tf32 row) * B(8x8 tf32 col) + D, fp32 accum
__device__ __forceinline__ void mma8(float d[4], const uint32_t a[4], uint32_t b0, uint32_t b1) {
    asm volatile(
        "mma.sync.aligned.m16n8k8.row.col.f32.tf32.tf32.f32 "
        "{%0,%1,%2,%3},{%4,%5,%6,%7},{%8,%9},{%0,%1,%2,%3};"
        : "+f"(d[0]), "+f"(d[1]), "+f"(d[2]), "+f"(d[3])
        : "r"(a[0]), "r"(a[1]), "r"(a[2]), "r"(a[3]), "r"(b0), "r"(b1));
}

// ---------------------------------------------------------------------------
// Transpose: out[C,R] = in[R,C]
// ---------------------------------------------------------------------------
__global__ __launch_bounds__(256) void transpose_kernel(const float* __restrict__ in,
                                                        float* __restrict__ out,
                                                        int R, int C) {
    __shared__ float t[32][33];
    const int bx = blockIdx.x * 32, by = blockIdx.y * 32;
    for (int i = threadIdx.y; i < 32; i += 8)
        t[i][threadIdx.x] = in[(size_t)(by + i) * C + bx + threadIdx.x];
    __syncthreads();
    for (int i = threadIdx.y; i < 32; i += 8)
        out[(size_t)(bx + i) * R + by + threadIdx.x] = t[threadIdx.x][i];
}

// ---------------------------------------------------------------------------
// mma.sync tf32 GEMM: C[M,N] = A[M,1024] @ Bt[N,1024]^T + bias
// 128x128 CTA tile, 256 thr (8 warps as 2x4), warp tile 64x32, BK=32.
// MODE 0: scatter into g_q/g_k/g_v; MODE 1: dense store.
// ---------------------------------------------------------------------------
template <int NTOT, int MODE>
__global__ __launch_bounds__(256) void mma_gemm(const float* __restrict__ A,
                                                const float* __restrict__ Bt,
                                                const float* __restrict__ bias,
                                                float* __restrict__ Cout) {
    constexpr int K = 1024;
    __shared__ uint32_t As[128][36];   // [m][k]
    __shared__ uint32_t Bs[128][36];   // [n][k]

    const int tid = threadIdx.x, lane = tid & 31, w = tid >> 5;
    const int bm = blockIdx.y * 128, bn = blockIdx.x * 128;
    const int wm = (w & 1) * 64, wn = (w >> 1) * 32;
    const int r = lane >> 2, c = lane & 3;

    float acc[4][4][4];
#pragma unroll
    for (int mi = 0; mi < 4; mi++)
#pragma unroll
        for (int ni = 0; ni < 4; ni++)
#pragma unroll
            for (int q = 0; q < 4; q++) acc[mi][ni][q] = 0.0f;

    for (int k0 = 0; k0 < K; k0 += 32) {
#pragma unroll
        for (int it = 0; it < 4; it++) {
            const int slot = tid + it * 256;
            const int row = slot >> 3, c4 = (slot & 7) * 4;
            float4 va = *reinterpret_cast<const float4*>(A + (size_t)(bm + row) * K + k0 + c4);
            As[row][c4 + 0] = f2tf32(va.x); As[row][c4 + 1] = f2tf32(va.y);
            As[row][c4 + 2] = f2tf32(va.z); As[row][c4 + 3] = f2tf32(va.w);
            float4 vb = *reinterpret_cast<const float4*>(Bt + (size_t)(bn + row) * K + k0 + c4);
            Bs[row][c4 + 0] = f2tf32(vb.x); Bs[row][c4 + 1] = f2tf32(vb.y);
            Bs[row][c4 + 2] = f2tf32(vb.z); Bs[row][c4 + 3] = f2tf32(vb.w);
        }
        __syncthreads();

#pragma unroll
        for (int ks = 0; ks < 4; ks++) {
            const int k = ks * 8;
            uint32_t af[4][4];
#pragma unroll
            for (int mi = 0; mi < 4; mi++) {
                af[mi][0] = As[wm + mi * 16 + r][k + c];
                af[mi][1] = As[wm + mi * 16 + 8 + r][k + c];
                af[mi][2] = As[wm + mi * 16 + r][k + c + 4];
                af[mi][3] = As[wm + mi * 16 + 8 + r][k + c + 4];
            }
            uint32_t bf[4][2];
#pragma unroll
            for (int ni = 0; ni < 4; ni++) {
                bf[ni][0] = Bs[wn + ni * 8 + r][k + c];
                bf[ni][1] = Bs[wn + ni * 8 + r][k + c + 4];
            }
#pragma unroll
            for (int mi = 0; mi < 4; mi++)
#pragma unroll
                for (int ni = 0; ni < 4; ni++)
                    mma8(acc[mi][ni], af[mi], bf[ni][0], bf[ni][1]);
        }
        __syncthreads();
    }

    // Epilogue
    const int c2 = (lane & 3) * 2;
#pragma unroll
    for (int mi = 0; mi < 4; mi++) {
#pragma unroll
        for (int ni = 0; ni < 4; ni++) {
            const int col = bn + wn + ni * 8 + c2;
            const float bi0 = bias[col], bi1 = bias[col + 1];
#pragma unroll
            for (int half = 0; half < 2; half++) {
                const int row = bm + wm + mi * 16 + r + half * 8;
                const float v0 = acc[mi][ni][half * 2 + 0] + bi0;
                const float v1 = acc[mi][ni][half * 2 + 1] + bi1;
                if (MODE == 0) {
                    const int which = col >> 10;
                    const int d     = col & 1023;
                    const int h     = d >> 6;
                    const int hd    = d & 63;
                    const int b     = row >> 11;
                    const int s     = row & 2047;
                    const size_t dst = (((size_t)b * H_ + h) * S_ + s) * HD_ + hd;
                    float2 v = {v0, v1};
                    if (which == 0)      *reinterpret_cast<float2*>(g_q + dst) = v;
                    else if (which == 1) *reinterpret_cast<float2*>(g_k + dst) = v;
                    else                 *reinterpret_cast<float2*>(g_v + dst) = v;
                } else {
                    float2 v = {v0, v1};
                    *reinterpret_cast<float2*>(Cout + (size_t)row * NTOT + col) = v;
                }
            }
        }
    }
}

// ---------------------------------------------------------------------------
// Flash attention with mma.sync tf32 — register softmax.
// CTA: 256 thr (8 warps), Br=128 q-rows, Bc=64 k-cols, HD=64.
// Warp w owns q-rows [w*16, w*16+16) for the whole kernel -> m/l in registers.
// S accumulator rows live in the 4 threads sharing r; row reductions are
// 2x shfl_xor. P is written tf32 to warp-private Ss, synced with __syncwarp.
// SMEM: Qs[128][68], Ks[64][68], Vs[64][68] (d-major), Ss[128][68]  = 104,448 B.
// ---------------------------------------------------------------------------
__global__ __launch_bounds__(256) void attn_mma() {
    extern __shared__ uint32_t smu[];
    uint32_t* Qs = smu;                    // [128][68]
    uint32_t* Ks = Qs + 128 * 68;          // [64][68]
    uint32_t* Vs = Ks + 64 * 68;           // [64][68]  (row=d, col=k)
    uint32_t* Ss = Vs + 64 * 68;           // [128][68] (tf32 P, warp-private rows)

    const int b  = blockIdx.z;
    const int h  = blockIdx.y;
    const int q0 = blockIdx.x * 128;

    const size_t head_off = ((size_t)b * H_ + h) * S_ * HD_;
    const float* Qg = g_q + head_off;
    const float* Kg = g_k + head_off;
    const float* Vg = g_v + head_off;

    const int tid = threadIdx.x, lane = tid & 31, w = tid >> 5;
    const int wrow = w * 16;
    const int r = lane >> 2, c = lane & 3;
    const int c2 = c * 2;

    // Load Q tile (128x64) once, tf32
#pragma unroll
    for (int it = 0; it < 8; it++) {
        const int slot = tid + it * 256;
        const int row = slot >> 4, c4 = (slot & 15) * 4;
        float4 v = *reinterpret_cast<const float4*>(Qg + (size_t)(q0 + row) * HD_ + c4);
        uint32_t* d = Qs + row * 68 + c4;
        d[0] = f2tf32(v.x); d[1] = f2tf32(v.y); d[2] = f2tf32(v.z); d[3] = f2tf32(v.w);
    }

    float m0 = -1e30f, m1 = -1e30f, l0 = 0.0f, l1 = 0.0f;
    float O[8][4];
#pragma unroll
    for (int ni = 0; ni < 8; ni++)
#pragma unroll
        for (int q = 0; q < 4; q++) O[ni][q] = 0.0f;

    for (int kt = 0; kt < S_; kt += 64) {
        __syncthreads();   // prev iteration's PV reads of Ks/Vs (and Ss stores) done
        // Load K (row=k-idx, col=d) and V transposed (row=d, col=k-idx)
#pragma unroll
        for (int it = 0; it < 4; it++) {
            const int slot = tid + it * 256;
            const int row = slot >> 4, c4 = (slot & 15) * 4;
            float4 kv = *reinterpret_cast<const float4*>(Kg + (size_t)(kt + row) * HD_ + c4);
            uint32_t* kd = Ks + row * 68 + c4;
            kd[0] = f2tf32(kv.x); kd[1] = f2tf32(kv.y); kd[2] = f2tf32(kv.z); kd[3] = f2tf32(kv.w);
            float4 vv = *reinterpret_cast<const float4*>(Vg + (size_t)(kt + row) * HD_ + c4);
            Vs[(c4 + 0) * 68 + row] = f2tf32(vv.x);
            Vs[(c4 + 1) * 68 + row] = f2tf32(vv.y);
            Vs[(c4 + 2) * 68 + row] = f2tf32(vv.z);
            Vs[(c4 + 3) * 68 + row] = f2tf32(vv.w);
        }
        __syncthreads();

        // S = Q @ K^T for this warp's 16 rows x 64 cols
        float sf[8][4];
#pragma unroll
        for (int ni = 0; ni < 8; ni++)
#pragma unroll
            for (int q = 0; q < 4; q++) sf[ni][q] = 0.0f;
#pragma unroll
        for (int ks = 0; ks < 8; ks++) {
            const int k = ks * 8;
            uint32_t af[4];
            af[0] = Qs[(wrow + r) * 68 + k + c];
            af[1] = Qs[(wrow + 8 + r) * 68 + k + c];
            af[2] = Qs[(wrow + r) * 68 + k + c + 4];
            af[3] = Qs[(wrow + 8 + r) * 68 + k + c + 4];
#pragma unroll
            for (int ni = 0; ni < 8; ni++) {
                uint32_t b0 = Ks[(ni * 8 + r) * 68 + k + c];
                uint32_t b1 = Ks[(ni * 8 + r) * 68 + k + c + 4];
                mma8(sf[ni], af, b0, b1);
            }
        }

        // ---- register softmax over the 4 c-threads of each row ----
        float mloc0 = -1e30f, mloc1 = -1e30f;
#pragma unroll
        for (int ni = 0; ni < 8; ni++) {
            sf[ni][0] *= SCALE_; sf[ni][1] *= SCALE_;
            sf[ni][2] *= SCALE_; sf[ni][3] *= SCALE_;
            mloc0 = fmaxf(mloc0, fmaxf(sf[ni][0], sf[ni][1]));
            mloc1 = fmaxf(mloc1, fmaxf(sf[ni][2], sf[ni][3]));
        }
        mloc0 = fmaxf(mloc0, __shfl_xor_sync(0xffffffffu, mloc0, 1));
        mloc0 = fmaxf(mloc0, __shfl_xor_sync(0xffffffffu, mloc0, 2));
        mloc1 = fmaxf(mloc1, __shfl_xor_sync(0xffffffffu, mloc1, 1));
        mloc1 = fmaxf(mloc1, __shfl_xor_sync(0xffffffffu, mloc1, 2));

        const float mnew0 = fmaxf(m0, mloc0);
        const float mnew1 = fmaxf(m1, mloc1);
        const float alpha0 = __expf(m0 - mnew0);
        const float alpha1 = __expf(m1 - mnew1);

        float ls0 = 0.0f, ls1 = 0.0f;
#pragma unroll
        for (int ni = 0; ni < 8; ni++) {
            const float p0 = __expf(sf[ni][0] - mnew0);
            const float p1 = __expf(sf[ni][1] - mnew0);
            const float p2 = __expf(sf[ni][2] - mnew1);
            const float p3 = __expf(sf[ni][3] - mnew1);
            ls0 += p0 + p1;
            ls1 += p2 + p3;
            uint2 u0 = {f2tf32(p0), f2tf32(p1)};
            uint2 u1 = {f2tf32(p2), f2tf32(p3)};
            *reinterpret_cast<uint2*>(Ss + (wrow + r) * 68 + ni * 8 + c2)     = u0;
            *reinterpret_cast<uint2*>(Ss + (wrow + 8 + r) * 68 + ni * 8 + c2) = u1;
        }
        ls0 += __shfl_xor_sync(0xffffffffu, ls0, 1);
        ls0 += __shfl_xor_sync(0xffffffffu, ls0, 2);
        ls1 += __shfl_xor_sync(0xffffffffu, ls1, 1);
        ls1 += __shfl_xor_sync(0xffffffffu, ls1, 2);

        l0 = l0 * alpha0 + ls0;  m0 = mnew0;
        l1 = l1 * alpha1 + ls1;  m1 = mnew1;

#pragma unroll
        for (int ni = 0; ni < 8; ni++) {
            O[ni][0] *= alpha0; O[ni][1] *= alpha0;
            O[ni][2] *= alpha1; O[ni][3] *= alpha1;
        }
        __syncwarp();   // P visible to all lanes of this warp

        // O += P @ V   (A frags from warp-private Ss rows)
#pragma unroll
        for (int ks = 0; ks < 8; ks++) {
            const int k = ks * 8;
            uint32_t af[4];
            af[0] = Ss[(wrow + r) * 68 + k + c];
            af[1] = Ss[(wrow + 8 + r) * 68 + k + c];
            af[2] = Ss[(wrow + r) * 68 + k + c + 4];
            af[3] = Ss[(wrow + 8 + r) * 68 + k + c + 4];
#pragma unroll
            for (int ni = 0; ni < 8; ni++) {
                uint32_t b0 = Vs[(ni * 8 + r) * 68 + k + c];
                uint32_t b1 = Vs[(ni * 8 + r) * 68 + k + c + 4];
                mma8(O[ni], af, b0, b1);
            }
        }
    }

    // Normalize and write out
    const float il0 = 1.0f / l0;
    const float il1 = 1.0f / l1;
#pragma unroll
    for (int ni = 0; ni < 8; ni++) {
        const int col = h * HD_ + ni * 8 + c2;
        const int row0 = q0 + wrow + r;
        float2 v0 = {O[ni][0] * il0, O[ni][1] * il0};
        float2 v1 = {O[ni][2] * il1, O[ni][3] * il1};
        *reinterpret_cast<float2*>(g_att + ((size_t)b * S_ + row0) * D_ + col)       = v0;
        *reinterpret_cast<float2*>(g_att + ((size_t)b * S_ + row0 + 8) * D_ + col)   = v1;
    }
}

// ---------------------------------------------------------------------------
extern "C" void kernel_launch(void* const* d_in, const int* in_sizes, int n_in,
                              void* d_out, int out_size) {
    (void)in_sizes; (void)n_in; (void)out_size;
    const float* x     = (const float*)d_in[0];
    const float* Wqkv  = (const float*)d_in[1];
    const float* bqkv  = (const float*)d_in[2];
    const float* Wproj = (const float*)d_in[3];
    const float* bproj = (const float*)d_in[4];
    float* out = (float*)d_out;

    float *att_dev = nullptr, *wqkvt_dev = nullptr, *wprojt_dev = nullptr;
    cudaGetSymbolAddress((void**)&att_dev,    g_att);
    cudaGetSymbolAddress((void**)&wqkvt_dev,  g_wqkvt);
    cudaGetSymbolAddress((void**)&wprojt_dev, g_wprojt);

    // Transpose weights to K-major [N,K]
    {
        dim3 blk(32, 8);
        transpose_kernel<<<dim3(3 * D_ / 32, D_ / 32), blk>>>(Wqkv, wqkvt_dev, D_, 3 * D_);
        transpose_kernel<<<dim3(D_ / 32, D_ / 32), blk>>>(Wproj, wprojt_dev, D_, D_);
    }

    // QKV GEMM (mma.sync tf32)
    {
        dim3 grid(3 * D_ / 128, (B_ * S_) / 128);
        mma_gemm<3 * D_, 0><<<grid, 256>>>(x, wqkvt_dev, bqkv, nullptr);
    }

    // Attention (mma.sync tf32, register softmax)
    {
        const int smem = (128 * 68 + 64 * 68 + 64 * 68 + 128 * 68) * 4;  // 104,448
        cudaFuncSetAttribute(attn_mma, cudaFuncAttributeMaxDynamicSharedMemorySize, smem);
        dim3 grid(S_ / 128, H_, B_);
        attn_mma<<<grid, 256, smem>>>();
    }

    // Output projection (mma.sync tf32)
    {
        dim3 grid(D_ / 128, (B_ * S_) / 128);
        mma_gemm<D_, 1><<<grid, 256>>>(att_dev, wprojt_dev, bproj, out);
    }
}